// round 5
// baseline (speedup 1.0000x reference)
#include <cuda_runtime.h>
#include <math.h>

// Problem shape (fixed by the reference): B=32, N=8192, D=128, fp32.
#define BATCH   32
#define NROWS   8192
#define DIM     128
#define CHUNKS  32
#define CHUNK   (NROWS / CHUNKS)   // 256 rows per CTA
#define WARPS   8                  // 256 threads
#define GROUP   4                  // rows per warp per iteration
#define NGROUPS (CHUNK / (WARPS * GROUP))  // 8

// Scratch (no allocations allowed -> __device__ globals)
__device__ float g_pm  [BATCH * CHUNKS];        // per-chunk max
__device__ float g_psum[BATCH * CHUNKS];        // per-chunk exp-sum
__device__ float g_pctx[BATCH * CHUNKS * DIM];  // per-chunk weighted ctx
__device__ int   g_count[BATCH];                // arrival counters (self-reset)

// ---------------------------------------------------------------------------
// Single fused kernel: one sweep over values (warp-per-row dot, online softmax
// accumulation), partials to scratch, then the LAST CTA per batch finalizes:
// merges partials -> context, and normalizes that batch's attn row in place.
// ---------------------------------------------------------------------------
__global__ void __launch_bounds__(256, 4)
attend_fused(const float* __restrict__ q,
             const float* __restrict__ v,
             float* __restrict__ attn,
             float* __restrict__ ctx_out)
{
    __shared__ float4 qs[DIM / 4];
    __shared__ float  sm_m[WARPS];
    __shared__ float  sm_sum[WARPS];
    __shared__ float  sm_ctx[WARPS][DIM];
    __shared__ int    s_last;

    const int b     = blockIdx.y;
    const int chunk = blockIdx.x;
    const int tid   = threadIdx.x;
    const int w     = tid >> 5;
    const int l     = tid & 31;
    const unsigned F = 0xffffffffu;

    if (tid < DIM / 4)
        qs[tid] = reinterpret_cast<const float4*>(q + (size_t)b * DIM)[tid];
    __syncthreads();

    const float4 q4 = qs[l];
    const float4* __restrict__ vb =
        reinterpret_cast<const float4*>(v + (size_t)b * NROWS * DIM);
    const size_t rowq = DIM / 4;

    const int base = chunk * CHUNK + w * GROUP;
    const bool hi = (l & 16) != 0;
    const bool b3 = (l & 8) != 0;

    float  m   = -INFINITY;
    float  sum = 0.0f;
    float4 ctx = make_float4(0.f, 0.f, 0.f, 0.f);

    float4 vreg[GROUP], vnext[GROUP];

    // prefetch group 0
    {
        const size_t r = (size_t)base;
        #pragma unroll
        for (int k = 0; k < GROUP; k++)
            vreg[k] = vb[(r + k) * rowq + l];
    }

    #pragma unroll 1
    for (int g = 0; g < NGROUPS; g++) {
        if (g + 1 < NGROUPS) {
            const size_t r = (size_t)base + (size_t)(g + 1) * (WARPS * GROUP);
            #pragma unroll
            for (int k = 0; k < GROUP; k++)
                vnext[k] = vb[(r + k) * rowq + l];
        }

        // per-lane partial dots for the 4 rows
        float p0 = vreg[0].x * q4.x + vreg[0].y * q4.y + vreg[0].z * q4.z + vreg[0].w * q4.w;
        float p1 = vreg[1].x * q4.x + vreg[1].y * q4.y + vreg[1].z * q4.z + vreg[1].w * q4.w;
        float p2 = vreg[2].x * q4.x + vreg[2].y * q4.y + vreg[2].z * q4.z + vreg[2].w * q4.w;
        float p3 = vreg[3].x * q4.x + vreg[3].y * q4.y + vreg[3].z * q4.z + vreg[3].w * q4.w;

        // merged 4-row reduction: 6 shuffles + 4 broadcasts (vs 20 butterfly)
        // xor16: rows {0,1} and {2,3} pairwise-merge
        float t01 = (hi ? p1 : p0) + __shfl_xor_sync(F, hi ? p0 : p1, 16);
        float t23 = (hi ? p3 : p2) + __shfl_xor_sync(F, hi ? p2 : p3, 16);
        // xor8: merge the two -> u holds row0@l0-7, row2@l8-15, row1@l16-23, row3@l24-31
        float u = (b3 ? t23 : t01) + __shfl_xor_sync(F, b3 ? t01 : t23, 8);
        u += __shfl_xor_sync(F, u, 4);
        u += __shfl_xor_sync(F, u, 2);
        u += __shfl_xor_sync(F, u, 1);

        float sc[GROUP];
        sc[0] = __shfl_sync(F, u, 0);
        sc[1] = __shfl_sync(F, u, 16);
        sc[2] = __shfl_sync(F, u, 8);
        sc[3] = __shfl_sync(F, u, 24);

        // stream raw scores (4 consecutive rows, 16B aligned)
        if (l == 0) {
            const size_t r = (size_t)base + (size_t)g * (WARPS * GROUP);
            *reinterpret_cast<float4*>(attn + (size_t)b * NROWS + r) =
                make_float4(sc[0], sc[1], sc[2], sc[3]);
        }

        // online softmax update (branch uniform across warp; new-max rare)
        #pragma unroll
        for (int k = 0; k < GROUP; k++) {
            const float s = sc[k];
            float wgt;
            if (s <= m) {
                wgt = __expf(s - m);
            } else {
                const float c = __expf(m - s);
                sum  *= c;
                ctx.x *= c; ctx.y *= c; ctx.z *= c; ctx.w *= c;
                m = s;
                wgt = 1.0f;
            }
            sum  += wgt;
            ctx.x += wgt * vreg[k].x;
            ctx.y += wgt * vreg[k].y;
            ctx.z += wgt * vreg[k].z;
            ctx.w += wgt * vreg[k].w;
        }

        #pragma unroll
        for (int k = 0; k < GROUP; k++)
            vreg[k] = vnext[k];
    }

    // CTA-level merge of 8 warp-partials -> chunk partials in global scratch
    if (l == 0) { sm_m[w] = m; sm_sum[w] = sum; }
    reinterpret_cast<float4*>(sm_ctx[w])[l] = ctx;
    __syncthreads();

    const int pidx = b * CHUNKS + chunk;
    if (tid < DIM) {
        float M = sm_m[0];
        #pragma unroll
        for (int i = 1; i < WARPS; i++) M = fmaxf(M, sm_m[i]);

        float c = 0.0f;
        #pragma unroll
        for (int i = 0; i < WARPS; i++)
            c += sm_ctx[i][tid] * __expf(sm_m[i] - M);

        g_pctx[(size_t)pidx * DIM + tid] = c;

        if (tid == 0) {
            float st = 0.0f;
            #pragma unroll
            for (int i = 0; i < WARPS; i++)
                st += sm_sum[i] * __expf(sm_m[i] - M);
            g_pm[pidx]   = M;
            g_psum[pidx] = st;
        }
    }

    // ---- arrival protocol (CUDA SDK threadfence-reduction pattern) ----
    __threadfence();
    if (tid == 0) {
        int old = atomicAdd(&g_count[b], 1);
        s_last = (old == CHUNKS - 1) ? 1 : 0;
    }
    __syncthreads();
    if (!s_last) return;

    if (tid == 0) g_count[b] = 0;   // self-reset for next graph replay

    // ---- finalizer: merge 32 chunk partials (L2-resident) ----
    float M = -INFINITY;
    #pragma unroll
    for (int c = 0; c < CHUNKS; c++)
        M = fmaxf(M, g_pm[b * CHUNKS + c]);

    float s = 0.0f;
    #pragma unroll
    for (int c = 0; c < CHUNKS; c++)
        s += g_psum[b * CHUNKS + c] * __expf(g_pm[b * CHUNKS + c] - M);
    const float inv = 1.0f / s;

    // context output (one dim per thread, threads 0..127)
    if (tid < DIM) {
        float acc = 0.0f;
        #pragma unroll
        for (int c = 0; c < CHUNKS; c++)
            acc += g_pctx[(size_t)(b * CHUNKS + c) * DIM + tid]
                 * __expf(g_pm[b * CHUNKS + c] - M);
        ctx_out[(size_t)b * DIM + tid] = acc * inv;
    }

    // normalize this batch's attn row in place: 8192 floats = 2048 float4
    float4* arow = reinterpret_cast<float4*>(attn + (size_t)b * NROWS);
    #pragma unroll
    for (int i = 0; i < (NROWS / 4) / 256; i++) {   // 8 iterations
        const int idx = i * 256 + tid;
        float4 a = arow[idx];
        a.x = __expf(a.x - M) * inv;
        a.y = __expf(a.y - M) * inv;
        a.z = __expf(a.z - M) * inv;
        a.w = __expf(a.w - M) * inv;
        arow[idx] = a;
    }
}

// ---------------------------------------------------------------------------
extern "C" void kernel_launch(void* const* d_in, const int* in_sizes, int n_in,
                              void* d_out, int out_size)
{
    // Identify inputs by size (queries: 32*1*128 = 4096; values: 32*8192*128)
    const float* q;
    const float* v;
    if (in_sizes[0] == BATCH * DIM) {
        q = (const float*)d_in[0];
        v = (const float*)d_in[1];
    } else {
        q = (const float*)d_in[1];
        v = (const float*)d_in[0];
    }

    float* attn = (float*)d_out;                          // [32, 8192]
    float* ctx  = (float*)d_out + (size_t)BATCH * NROWS;  // [32, 128]

    dim3 grid(CHUNKS, BATCH);
    attend_fused<<<grid, 256>>>(q, v, attn, ctx);
}